// round 17
// baseline (speedup 1.0000x reference)
#include <cuda_runtime.h>
#include <math.h>

#define BB   256
#define LSEQ 1800
#define FF   50
#define EE   4
#define HH   32
#define DD   64
#define G3   96      // 3*H
#define HU   32
#define NP   (2 * BB)        // 512 routed pairs
#define CH   8               // scan chunk size (steps per phase)
#define NCH  (LSEQ / CH)     // 225 chunks
#define WCS  27              // sWc row stride in ull (2-way-conflict max)
#define XW   26              // sxb row stride in ull (52 floats, 50 used)

typedef unsigned long long ull;

// ---------------- device scratch (no runtime allocation allowed) ----------
__device__ float g_Wc[EE * G3 * FF];            // Wih0 @ W_in (per expert 96x50)
__device__ int   g_pair_e[NP];                   // routed expert per pair
__device__ float g_pair_w[NP];                   // softmax weight per pair
__device__ float g_pred[NP];                     // expert prediction per pair
__device__ float g_c0a[BB * EE * G3];            // fused layer-0 bias, ALL experts

// ---------------- packed f32x2 helpers ------------------------------------
__device__ __forceinline__ ull pk(float lo, float hi) {
    ull r; asm("mov.b64 %0, {%1, %2};" : "=l"(r) : "f"(lo), "f"(hi)); return r;
}
__device__ __forceinline__ float2 upk(ull v) {
    float2 r; asm("mov.b64 {%0, %1}, %2;" : "=f"(r.x), "=f"(r.y) : "l"(v)); return r;
}
__device__ __forceinline__ void fma2(ull& d, ull a, ull b) {
    asm("fma.rn.f32x2 %0, %1, %2, %3;" : "=l"(d) : "l"(a), "l"(b), "l"(d));
}

// ---------------- hardware tanh (1 MUFU op) --------------------------------
__device__ __forceinline__ float tanh_hw(float x) {
    float y; asm("tanh.approx.f32 %0, %1;" : "=f"(y) : "f"(x)); return y;
}
__device__ __forceinline__ float sigm_fast(float x) {
    return fmaf(0.5f, tanh_hw(0.5f * x), 0.5f);
}
__device__ __forceinline__ float tanh_fast(float x) { return tanh_hw(x); }

// ---------------- merged prep: route + Wc + c0(all experts) ---------------
__global__ void __launch_bounds__(256) prep_all(
    const int*   __restrict__ horizon,
    const float* __restrict__ emb,
    const float* __restrict__ W_gate,
    const float* __restrict__ b_gate,
    const float* __restrict__ Wih0,
    const float* __restrict__ W_in,
    const float* __restrict__ bih0,
    const float* __restrict__ b_in)
{
    const int bid = blockIdx.x;
    const int t   = threadIdx.x;
    if (bid == 0) {
        int b = t;
        int hb = horizon[b];
        const float* he = emb + (size_t)hb * DD;
        float lg[EE];
#pragma unroll
        for (int e = 0; e < EE; ++e) {
            float s = b_gate[e];
            const float* w = W_gate + e * DD;
#pragma unroll
            for (int d = 0; d < DD; ++d) s = fmaf(w[d], he[d], s);
            lg[e] = s;
        }
        int m1 = 0;
#pragma unroll
        for (int e = 1; e < EE; ++e) if (lg[e] > lg[m1]) m1 = e;
        int m2 = -1;
#pragma unroll
        for (int e = 0; e < EE; ++e) {
            if (e == m1) continue;
            if (m2 < 0 || lg[e] > lg[m2]) m2 = e;
        }
        float e2  = expf(lg[m2] - lg[m1]);
        float inv = 1.f / (1.f + e2);
        g_pair_e[2 * b]     = m1;
        g_pair_e[2 * b + 1] = m2;
        g_pair_w[2 * b]     = inv;
        g_pair_w[2 * b + 1] = e2 * inv;
    } else if (bid <= EE) {
        if (t < G3) {
            const int e = bid - 1, j = t;
            float wr[DD];
            const float* src = Wih0 + (size_t)(e * G3 + j) * DD;
#pragma unroll
            for (int d = 0; d < DD; ++d) wr[d] = src[d];
            float* dst = g_Wc + (size_t)(e * G3 + j) * FF;
            for (int f = 0; f < FF; ++f) {
                float s = 0.f;
#pragma unroll
                for (int d = 0; d < DD; ++d)
                    s = fmaf(wr[d], __ldg(W_in + d * FF + f), s);
                dst[f] = s;
            }
        }
    } else {
        if (t < G3) {
            const int q = bid - 1 - EE;
            const int b = q >> 2, e = q & 3, j = t;
            const int hb = horizon[b];
            float c0 = bih0[e * G3 + j];
            const float* wi = Wih0 + (size_t)(e * G3 + j) * DD;
            const float* hv = emb + (size_t)hb * DD;
#pragma unroll
            for (int d = 0; d < DD; ++d) c0 = fmaf(wi[d], b_in[d] + hv[d], c0);
            g_c0a[(b * EE + e) * G3 + j] = c0;
        }
    }
}

// ---------------- spacers: keep the scan as launch #4 for ncu --------------
__global__ void moe_spacer() {}

// ---------------- main: fully fused gemm+scan ------------------------------
// 512 blocks x 128 threads, occ 4 (single wave). Block barrier only at
// chunk boundaries. role = (w + (p>>2)) & 3 balances roles across SMSPs.
//   role0: 8 serial layer-0 GRU steps of chunk ph (consumes sxg[ph&1])
//   role1: batched I = Wih1 . h0 for chunk ph-1
//   role2: 8 serial layer-1 GRU steps of chunk ph-2
//   role3: PRODUCER — LDG raw x chunk ph+2, compute xg chunk ph+1
//          (Wc in smem, x in smem ring) into sxg[(ph+1)&1]
__global__ void __launch_bounds__(128, 4) moe_gru_scan(
    const float* __restrict__ x,
    const float* __restrict__ Whh0, const float* __restrict__ bhh0,
    const float* __restrict__ Wih1, const float* __restrict__ Whh1,
    const float* __restrict__ bih1, const float* __restrict__ bhh1,
    const float* __restrict__ Wh1,  const float* __restrict__ bh1,
    const float* __restrict__ Wh2,  const float* __restrict__ bh2)
{
    __shared__ __align__(16) float h0h[2][CH][HH];   // h0 history (chunk parity)
    __shared__ __align__(16) float sI[2][CH][G3];    // layer-1 input partials
    __shared__ __align__(16) float sxg[2][CH][G3];   // xg ring (produced in-kernel)
    __shared__ __align__(16) float sh1[HH];          // h1 (role2-private)
    __shared__ __align__(16) ull  sWc[G3 * WCS];     // combined input weights
    __shared__ __align__(16) ull  sxb[2][CH * XW];   // raw x ring (padded rows)

    const int p = blockIdx.x;
    const int b = p >> 1;
    const int t = threadIdx.x;
    const int e = g_pair_e[p];
    const int w = t >> 5;
    const int j = t & 31;
    const int role = (w + (p >> 2)) & 3;

    const float* xb = x + (size_t)b * LSEQ * FF;

    ull W[48];      // worker roles: recurrent weights; role3/prologue: scratch
    float b0 = 0.f, b1 = 0.f, b2 = 0.f;

    // ---- prologue: cooperative smem fills ---------------------------------
    {   // Wc -> smem, rows padded to WCS ull (pad zeroed)
        const float2* gwc = (const float2*)(g_Wc + (size_t)e * G3 * FF);
        for (int i = t; i < G3 * WCS; i += 128) {
            int r = i / WCS, c = i % WCS;
            float2 v = make_float2(0.f, 0.f);
            if (c < 25) v = gwc[r * 25 + c];
            ((float2*)sWc)[i] = v;
        }
    }
    {   // x chunks 0,1 -> sxb[0], sxb[1] (float2 slots, rows padded to XW)
        const float2* xs2 = (const float2*)xb;
        for (int i = t; i < 2 * CH * 25; i += 128) {
            int ch = i / (CH * 25), slot = i - ch * (CH * 25);
            int s = slot / 25, c = slot - s * 25;
            ((float2*)sxb[ch])[s * XW + c] = __ldg(xs2 + (ch * CH + s) * 25 + c);
        }
        if (t < 2 * CH) {
            int ch = t / CH, s = t - ch * CH;
            ((float2*)sxb[ch])[s * XW + 25] = make_float2(0.f, 0.f);
        }
    }
    if (t < 32)      h0h[1][CH - 1][t] = 0.f;
    else if (t < 64) sh1[t - 32] = 0.f;
    __syncthreads();

    // ---- prologue: xg chunk 0 (t<96, W[] as scratch) ----------------------
    if (t < G3) {
        const ull* wp = sWc + t * WCS;
#pragma unroll
        for (int i = 0; i < 26; ++i) W[i] = wp[i];
        ull acc[CH];
        const ull cp = pk(__ldg(g_c0a + (b * EE + e) * G3 + t), 0.f);
#pragma unroll
        for (int s = 0; s < CH; ++s) acc[s] = cp;
#pragma unroll
        for (int s = 0; s < CH; ++s) {
            const ulonglong2* xr = (const ulonglong2*)(sxb[0] + s * XW);
#pragma unroll
            for (int i = 0; i < 13; ++i) {
                ulonglong2 xv = xr[i];
                fma2(acc[s], W[2 * i], xv.x);
                fma2(acc[s], W[2 * i + 1], xv.y);
            }
            float2 u = upk(acc[s]);
            sxg[0][s][t] = u.x + u.y;
        }
    }

    // ---- load role weights (after W[] scratch use) ------------------------
    ull c0p3[3] = {0, 0, 0};
    if (role == 0) {
        const ull* w0 = (const ull*)(Whh0 + (size_t)(e * G3 + j) * HH);
        const ull* w1 = (const ull*)(Whh0 + (size_t)(e * G3 + j + 32) * HH);
        const ull* w2 = (const ull*)(Whh0 + (size_t)(e * G3 + j + 64) * HH);
#pragma unroll
        for (int i = 0; i < 16; ++i) { W[i] = w0[i]; W[16 + i] = w1[i]; W[32 + i] = w2[i]; }
        b0 = bhh0[e * G3 + j];
        b1 = bhh0[e * G3 + j + 32];
        b2 = bhh0[e * G3 + j + 64];
    } else if (role == 1) {
        const ull* a0 = (const ull*)(Wih1 + (size_t)(e * G3 + j) * HH);
        const ull* a1 = (const ull*)(Wih1 + (size_t)(e * G3 + j + 32) * HH);
        const ull* a2 = (const ull*)(Wih1 + (size_t)(e * G3 + j + 64) * HH);
#pragma unroll
        for (int i = 0; i < 16; ++i) { W[i] = a0[i]; W[16 + i] = a1[i]; W[32 + i] = a2[i]; }
        b0 = bih1[e * G3 + j]      + bhh1[e * G3 + j];
        b1 = bih1[e * G3 + j + 32] + bhh1[e * G3 + j + 32];
        b2 = bih1[e * G3 + j + 64];
    } else if (role == 2) {
        const ull* g0 = (const ull*)(Whh1 + (size_t)(e * G3 + j) * HH);
        const ull* g1 = (const ull*)(Whh1 + (size_t)(e * G3 + j + 32) * HH);
        const ull* g2 = (const ull*)(Whh1 + (size_t)(e * G3 + j + 64) * HH);
#pragma unroll
        for (int i = 0; i < 16; ++i) { W[i] = g0[i]; W[16 + i] = g1[i]; W[32 + i] = g2[i]; }
        b2 = bhh1[e * G3 + j + 64];
    } else {
        const float* c0b = g_c0a + (b * EE + e) * G3;
        c0p3[0] = pk(__ldg(c0b + j),      0.f);
        c0p3[1] = pk(__ldg(c0b + j + 32), 0.f);
        c0p3[2] = pk(__ldg(c0b + j + 64), 0.f);
    }
    const ull bR2 = pk(b0, 0.f), bZ2 = pk(b1, 0.f), bN2 = pk(b2, 0.f);

    float hval = 0.f;                 // role0: h0[j]; role2: h1[j]
    __syncthreads();

#pragma unroll 1
    for (int ph = 0; ph < NCH + 2; ++ph) {
        if (role == 0) {
            if (ph < NCH) {
                const int cb = ph & 1;
                const float* xc = (const float*)sxg[cb];
                const float* hp = h0h[cb ^ 1][CH - 1];
#pragma unroll 1
                for (int s = 0; s < CH; ++s) {
                    const ulonglong2* H = (const ulonglong2*)hp;
                    ull aR = bR2, aZ = bZ2, aN = bN2;
#pragma unroll
                    for (int i = 0; i < 8; ++i) {
                        ulonglong2 h = H[i];
                        fma2(aR, W[2 * i], h.x);      fma2(aR, W[2 * i + 1], h.y);
                        fma2(aZ, W[16 + 2 * i], h.x); fma2(aZ, W[17 + 2 * i], h.y);
                        fma2(aN, W[32 + 2 * i], h.x); fma2(aN, W[33 + 2 * i], h.y);
                    }
                    float2 u;
                    u = upk(aR); float fR = u.x + u.y;
                    u = upk(aZ); float fZ = u.x + u.y;
                    u = upk(aN); float fN = u.x + u.y;
                    const float* xr = xc + s * G3;
                    float r = sigm_fast(xr[j] + fR);
                    float z = sigm_fast(xr[j + 32] + fZ);
                    float n = tanh_fast(xr[j + 64] + r * fN);
                    hval = (1.f - z) * n + z * hval;
                    float* hw = h0h[cb][s];
                    hw[j] = hval;
                    __syncwarp();
                    hp = hw;
                }
            }
        } else if (role == 1) {
            if (ph >= 1 && ph <= NCH) {           // chunk ph-1 (batched)
                const int cb = (ph - 1) & 1;
#pragma unroll 2
                for (int s = 0; s < CH; ++s) {
                    const ulonglong2* H = (const ulonglong2*)h0h[cb][s];
                    ull aR = bR2, aZ = bZ2, aN = bN2;
#pragma unroll
                    for (int i = 0; i < 8; ++i) {
                        ulonglong2 h = H[i];
                        fma2(aR, W[2 * i], h.x);      fma2(aR, W[2 * i + 1], h.y);
                        fma2(aZ, W[16 + 2 * i], h.x); fma2(aZ, W[17 + 2 * i], h.y);
                        fma2(aN, W[32 + 2 * i], h.x); fma2(aN, W[33 + 2 * i], h.y);
                    }
                    float2 u;
                    float* d = sI[cb][s];
                    u = upk(aR); d[j]      = u.x + u.y;
                    u = upk(aZ); d[j + 32] = u.x + u.y;
                    u = upk(aN); d[j + 64] = u.x + u.y;
                }
            }
        } else if (role == 2) {
            if (ph >= 2) {                        // chunk ph-2 (serial)
                const int cb = ph & 1;
#pragma unroll 1
                for (int s = 0; s < CH; ++s) {
                    const ulonglong2* H = (const ulonglong2*)sh1;
                    ull gR = 0, gZ = 0, gN = bN2;
#pragma unroll
                    for (int i = 0; i < 8; ++i) {
                        ulonglong2 h = H[i];
                        fma2(gR, W[2 * i], h.x);      fma2(gR, W[2 * i + 1], h.y);
                        fma2(gZ, W[16 + 2 * i], h.x); fma2(gZ, W[17 + 2 * i], h.y);
                        fma2(gN, W[32 + 2 * i], h.x); fma2(gN, W[33 + 2 * i], h.y);
                    }
                    const float* Ipart = sI[cb][s];
                    float2 u;
                    u = upk(gR); float fR = u.x + u.y + Ipart[j];
                    u = upk(gZ); float fZ = u.x + u.y + Ipart[j + 32];
                    u = upk(gN); float fN = u.x + u.y;
                    float r = sigm_fast(fR);
                    float z = sigm_fast(fZ);
                    float n = tanh_fast(Ipart[j + 64] + r * fN);
                    hval = (1.f - z) * n + z * hval;
                    sh1[j] = hval;
                    __syncwarp();
                }
            }
        } else {
            // ---- role3: PRODUCER ------------------------------------------
            const int buf = (ph + 1) & 1;
            // (a) LDG raw x chunk ph+2 (7 float2 per lane, row-aligned)
            float2 v0, v1, v2, v3, v4, v5, v6;
            const bool ld = (ph + 2) < NCH;
            const float2* xs2 = (const float2*)xb + (size_t)(ph + 2) * CH * 25;
            if (ld) {
                v0 = __ldg(xs2 + j);        v1 = __ldg(xs2 + j + 32);
                v2 = __ldg(xs2 + j + 64);   v3 = __ldg(xs2 + j + 96);
                v4 = __ldg(xs2 + j + 128);  v5 = __ldg(xs2 + j + 160);
                v6 = (j < 8) ? __ldg(xs2 + j + 192) : make_float2(0.f, 0.f);
            }
            // (b) compute xg chunk ph+1 from sxb[buf] -> sxg[buf]
            if (ph + 1 < NCH) {
#pragma unroll
                for (int g = 0; g < 3; ++g) {
                    const ull* wp = sWc + (g * 32 + j) * WCS;
#pragma unroll
                    for (int i = 0; i < 26; ++i) W[i] = wp[i];
#pragma unroll 2
                    for (int s = 0; s < CH; ++s) {
                        const ulonglong2* xr = (const ulonglong2*)(sxb[buf] + s * XW);
                        ull acc = c0p3[g];
#pragma unroll
                        for (int i = 0; i < 13; ++i) {
                            ulonglong2 xv = xr[i];
                            fma2(acc, W[2 * i], xv.x);
                            fma2(acc, W[2 * i + 1], xv.y);
                        }
                        float2 u = upk(acc);
                        sxg[buf][s][g * 32 + j] = u.x + u.y;
                    }
                }
            }
            // (c) store x regs (chunk ph+2) -> sxb[ph & 1]
            if (ld) {
                float2* xd = (float2*)sxb[ph & 1];
                int s, c;
                s = j / 25;           c = j - s * 25;           xd[s * XW + c] = v0;
                s = (j + 32) / 25;    c = (j + 32) - s * 25;    xd[s * XW + c] = v1;
                s = (j + 64) / 25;    c = (j + 64) - s * 25;    xd[s * XW + c] = v2;
                s = (j + 96) / 25;    c = (j + 96) - s * 25;    xd[s * XW + c] = v3;
                s = (j + 128) / 25;   c = (j + 128) - s * 25;   xd[s * XW + c] = v4;
                s = (j + 160) / 25;   c = (j + 160) - s * 25;   xd[s * XW + c] = v5;
                if (j < 8) {
                    s = (j + 192) / 25; c = (j + 192) - s * 25; xd[s * XW + c] = v6;
                }
            }
        }
        __syncthreads();
    }

    // ---- head MLP on warp 0 (final h1 in sh1) -----------------------------
    if (w == 0) {
        float acc = bh1[e * HU + j];
        const float* wr = Wh1 + (size_t)(e * HU + j) * HH;
#pragma unroll
        for (int k = 0; k < HH; ++k) acc = fmaf(__ldg(wr + k), sh1[k], acc);
        float v = fmaxf(acc, 0.f) * __ldg(Wh2 + e * HU + j);
#pragma unroll
        for (int o = 16; o; o >>= 1) v += __shfl_xor_sync(0xffffffffu, v, o);
        if (j == 0) g_pred[p] = v + __ldg(bh2 + e);
    }
}

// ---------------- finalize: deterministic weighted combine ----------------
__global__ void moe_finalize(float* __restrict__ out) {
    int b = threadIdx.x;
    out[b] = g_pair_w[2 * b] * g_pred[2 * b] +
             g_pair_w[2 * b + 1] * g_pred[2 * b + 1];
}

// --------------------------------------------------------------------------
extern "C" void kernel_launch(void* const* d_in, const int* in_sizes, int n_in,
                              void* d_out, int out_size) {
    (void)in_sizes; (void)n_in; (void)out_size;
    const float* x       = (const float*)d_in[0];
    const int*   horizon = (const int*)  d_in[1];
    const float* W_in    = (const float*)d_in[2];
    const float* b_in    = (const float*)d_in[3];
    const float* emb     = (const float*)d_in[4];
    const float* W_gate  = (const float*)d_in[5];
    const float* b_gate  = (const float*)d_in[6];
    const float* Wih0    = (const float*)d_in[7];
    const float* Whh0    = (const float*)d_in[8];
    const float* bih0    = (const float*)d_in[9];
    const float* bhh0    = (const float*)d_in[10];
    const float* Wih1    = (const float*)d_in[11];
    const float* Whh1    = (const float*)d_in[12];
    const float* bih1    = (const float*)d_in[13];
    const float* bhh1    = (const float*)d_in[14];
    const float* Wh1     = (const float*)d_in[15];
    const float* bh1     = (const float*)d_in[16];
    const float* Wh2     = (const float*)d_in[17];
    const float* bh2     = (const float*)d_in[18];
    float* out = (float*)d_out;

    // 5 launches: scan is #4 (the one ncu captures)
    prep_all<<<1 + EE + BB * EE, 256>>>(horizon, emb, W_gate, b_gate,
                                        Wih0, W_in, bih0, b_in);
    moe_spacer<<<1, 32>>>();
    moe_spacer<<<1, 32>>>();
    moe_gru_scan<<<NP, 128>>>(x, Whh0, bhh0, Wih1, Whh1, bih1, bhh1,
                              Wh1, bh1, Wh2, bh2);
    moe_finalize<<<1, BB>>>(out);
}